// round 6
// baseline (speedup 1.0000x reference)
#include <cuda_runtime.h>
#include <cuda_fp16.h>
#include <cstdint>

#define BB 8
#define LL 2048
#define HH 256
#define M_TOT (BB*LL)

// Scratch (static device globals — allocation-free, graph-capture legal)
__device__ __half g_Q[M_TOT*HH];          // [b*L + q][h], pre-scaled by 1/sqrt(H)
__device__ __half g_K[M_TOT*HH];          // [b*L + k][h]
__device__ __half g_Vt[BB*HH*LL];         // TRANSPOSED: [b][d][kv]

// ---------------------------------------------------------------------------
// Helpers
// ---------------------------------------------------------------------------
__device__ __forceinline__ void mma_f16(float c[4], const uint32_t a[4], const uint32_t b[2]) {
    asm volatile(
        "mma.sync.aligned.m16n8k16.row.col.f32.f16.f16.f32 "
        "{%0,%1,%2,%3}, {%4,%5,%6,%7}, {%8,%9}, {%0,%1,%2,%3};"
        : "+f"(c[0]), "+f"(c[1]), "+f"(c[2]), "+f"(c[3])
        : "r"(a[0]), "r"(a[1]), "r"(a[2]), "r"(a[3]), "r"(b[0]), "r"(b[1]));
}
__device__ __forceinline__ void cp16(__half* s, const __half* g) {
    uint32_t sa = (uint32_t)__cvta_generic_to_shared(s);
    asm volatile("cp.async.cg.shared.global [%0], [%1], 16;" :: "r"(sa), "l"(g));
}
#define CP_COMMIT() asm volatile("cp.async.commit_group;" ::: "memory")
#define CP_WAIT1()  asm volatile("cp.async.wait_group 1;" ::: "memory")
__device__ __forceinline__ uint32_t ldh2(const __half* p) { return *(const uint32_t*)p; }

// ---------------------------------------------------------------------------
// Kernel 1: QKV projection, y = x @ W^T, fp16 mma (m16n8k16), fp32 accum.
// Q output pre-scaled by 1/sqrt(H). V output written TRANSPOSED via smem stage.
// grid (M_TOT/64, HH/64, 3), block 256 (8 warps, 4m x 2n of a 64x64 tile).
// (unchanged from R5 — measured working at ~47us)
// ---------------------------------------------------------------------------
__global__ __launch_bounds__(256, 2)
void proj_kernel(const float* __restrict__ x,
                 const float* __restrict__ Wq,
                 const float* __restrict__ Wk,
                 const float* __restrict__ Wv,
                 const int* __restrict__ lens)
{
    const int mtile = blockIdx.x, ntile = blockIdx.y, which = blockIdx.z;
    const float* Wp = (which == 0) ? Wq : (which == 1) ? Wk : Wv;

    if (which != 0) {
        int m0 = mtile * 64;
        int b = m0 / LL, pos = m0 % LL;
        if (pos >= lens[b]) return;
    }

    __shared__ __half Xs[64][72];   // stride 72 halves = 36 words ≡ 4 mod 32
    __shared__ __half Ws[64][72];

    const int tid = threadIdx.x;
    const int lane = tid & 31, warp = tid >> 5;
    const int wm = warp & 3, wn = warp >> 2;   // 4 x 2 warp grid

    float acc[4][4];
    #pragma unroll
    for (int i = 0; i < 4; i++)
        #pragma unroll
        for (int j = 0; j < 4; j++) acc[i][j] = 0.f;

    for (int kc = 0; kc < HH; kc += 64) {
        #pragma unroll
        for (int it = 0; it < 4; it++) {
            int idx = tid + it * 256;          // 1024 float4 per operand
            int r = idx >> 4, c4 = (idx & 15) * 4;
            float4 xv = *(const float4*)&x[(size_t)(mtile * 64 + r) * HH + kc + c4];
            float4 wv = *(const float4*)&Wp[(size_t)(ntile * 64 + r) * HH + kc + c4];
            *(__half2*)&Xs[r][c4]     = __floats2half2_rn(xv.x, xv.y);
            *(__half2*)&Xs[r][c4 + 2] = __floats2half2_rn(xv.z, xv.w);
            *(__half2*)&Ws[r][c4]     = __floats2half2_rn(wv.x, wv.y);
            *(__half2*)&Ws[r][c4 + 2] = __floats2half2_rn(wv.z, wv.w);
        }
        __syncthreads();

        #pragma unroll
        for (int ks = 0; ks < 4; ks++) {       // k-steps of 16
            const int ar = wm * 16 + (lane >> 2);
            const int k0 = ks * 16 + (lane & 3) * 2;
            uint32_t a[4];
            a[0] = ldh2(&Xs[ar][k0]);
            a[1] = ldh2(&Xs[ar + 8][k0]);
            a[2] = ldh2(&Xs[ar][k0 + 8]);
            a[3] = ldh2(&Xs[ar + 8][k0 + 8]);
            #pragma unroll
            for (int nf = 0; nf < 4; nf++) {
                int br = wn * 32 + nf * 8 + (lane >> 2);
                uint32_t b[2];
                b[0] = ldh2(&Ws[br][k0]);
                b[1] = ldh2(&Ws[br][k0 + 8]);
                mma_f16(acc[nf], a, b);
            }
        }
        __syncthreads();
    }

    if (which != 2) {
        __half* outp = (which == 0) ? g_Q : g_K;
        const float scl = (which == 0) ? 0.0625f : 1.0f;
        const int r0 = mtile * 64 + wm * 16 + (lane >> 2);
        #pragma unroll
        for (int nf = 0; nf < 4; nf++) {
            int c0 = ntile * 64 + wn * 32 + nf * 8 + 2 * (lane & 3);
            *(__half2*)&outp[(size_t)r0 * HH + c0] =
                __floats2half2_rn(acc[nf][0] * scl, acc[nf][1] * scl);
            *(__half2*)&outp[(size_t)(r0 + 8) * HH + c0] =
                __floats2half2_rn(acc[nf][2] * scl, acc[nf][3] * scl);
        }
    } else {
        // V: stage tile in smem (reuse Xs), then write transposed [d][kv]
        const int rl = wm * 16 + (lane >> 2);
        #pragma unroll
        for (int nf = 0; nf < 4; nf++) {
            int cl = wn * 32 + nf * 8 + 2 * (lane & 3);
            *(__half2*)&Xs[rl][cl]     = __floats2half2_rn(acc[nf][0], acc[nf][1]);
            *(__half2*)&Xs[rl + 8][cl] = __floats2half2_rn(acc[nf][2], acc[nf][3]);
        }
        __syncthreads();
        const int d = tid >> 2, part = tid & 3;         // 64 d-rows x 4 parts
        const int m0 = mtile * 64;
        const int b = m0 >> 11, kvb = m0 & 2047;
        __align__(16) __half tmp[16];
        #pragma unroll
        for (int i = 0; i < 16; i++) tmp[i] = Xs[part * 16 + i][d];
        size_t vb = (size_t)b * HH * LL + (size_t)(ntile * 64 + d) * LL + kvb + part * 16;
        *(uint4*)&g_Vt[vb]     = *(uint4*)&tmp[0];
        *(uint4*)&g_Vt[vb + 8] = *(uint4*)&tmp[8];
    }
}

// ---------------------------------------------------------------------------
// Kernel 2: flash attention, fp16 operands, fp32 softmax/accum.
// grid (LL/32, BB), block 256 (8 warps), 101.2 KB smem -> 2 CTAs per SM.
// Two co-resident CTAs desynchronize: one CTA's softmax/barrier window is
// covered by the other CTA's mma stream. Per-warp work shapes identical to R5.
// Q tile = 32 rows; K/V tiles = 64 kv rows, cp.async pipelined as before.
// ---------------------------------------------------------------------------
#define QKS 264   // Q/K row stride (halves): 132 words ≡ 4 mod 32, conflict-free
#define VTS 72    // Vt row stride (halves): 36 words ≡ 4 mod 32
#define SSF 68    // S row stride (floats)
#define PSS 72    // P row stride (halves)

#define OFF_KS  16896                      // Qs: 32*264*2
#define OFF_VT  50688                      // Ks: 64*264*2
#define OFF_SS  87552                      // Vts: 256*72*2
#define OFF_PS  96256                      // Ss: 32*68*4
#define OFF_ST  100864                     // Ps: 32*72*2
#define ATTN_SMEM_BYTES 101248             // + stats 384

__global__ __launch_bounds__(256, 2)
void attn_kernel(const int* __restrict__ lens, float* __restrict__ out)
{
    extern __shared__ unsigned char smr[];
    __half* Qs  = (__half*)smr;
    __half* Ks  = (__half*)(smr + OFF_KS);
    __half* Vts = (__half*)(smr + OFF_VT);
    float*  Ss  = (float*)(smr + OFF_SS);
    __half* Ps  = (__half*)(smr + OFF_PS);
    float*  rowm = (float*)(smr + OFF_ST);
    float*  rowl = rowm + 32;
    float*  rowa = rowl + 32;

    const int qt = blockIdx.x, b = blockIdx.y;         // qt: 32-row tile index
    const int len = lens[b];
    const int tid = threadIdx.x, lane = tid & 31, warp = tid >> 5;
    const int wm = warp & 1, wn = warp >> 1;           // 2 x 4 warp grid
    const size_t kbase = (size_t)b * LL * HH;
    const size_t vtb   = (size_t)b * HH * LL;
    const int nkt = (len + 63) >> 6;

    // Prologue: async-load K0 (group0) and Vt0 (group1)
    #pragma unroll
    for (int it = 0; it < 8; it++) {
        int idx = tid + it * 256;                      // 2048 uint4
        int r = idx >> 5, c8 = (idx & 31) * 8;
        cp16(&Ks[r * QKS + c8], &g_K[kbase + (size_t)r * HH + c8]);
    }
    CP_COMMIT();
    #pragma unroll
    for (int it = 0; it < 8; it++) {
        int idx = tid + it * 256;                      // 256 d-rows x 8 chunks
        int r = idx >> 3, c8 = (idx & 7) * 8;
        cp16(&Vts[r * VTS + c8], &g_Vt[vtb + (size_t)r * LL + c8]);
    }
    CP_COMMIT();

    // Q tile (32 x 256 halves), already pre-scaled in projection
    #pragma unroll
    for (int it = 0; it < 4; it++) {
        int idx = tid + it * 256;                      // 1024 uint4
        int r = idx >> 5, c8 = (idx & 31) * 8;
        *(uint4*)&Qs[r * QKS + c8] =
            *(const uint4*)&g_Q[kbase + (size_t)(qt * 32 + r) * HH + c8];
    }
    if (tid < 32) { rowm[tid] = -1e30f; rowl[tid] = 0.f; }

    // O accumulators: warp owns rows [wm*16,+16), cols [wn*64,+64) -> 8 n-frags
    float o[8][4];
    #pragma unroll
    for (int i = 0; i < 8; i++)
        #pragma unroll
        for (int j = 0; j < 4; j++) o[i][j] = 0.f;

    for (int kt = 0; kt < nkt; kt++) {
        CP_WAIT1();            // K[t] done (Vt[t] may still be in flight)
        __syncthreads();

        // ---- S = Q K^T : warp rows [wm*16,+16), cols [wn*16,+16), k-dim 256
        float s[2][4];
        #pragma unroll
        for (int i = 0; i < 2; i++)
            #pragma unroll
            for (int j = 0; j < 4; j++) s[i][j] = 0.f;

        #pragma unroll
        for (int ks = 0; ks < 16; ks++) {              // k-steps of 16
            const int ar = wm * 16 + (lane >> 2);
            const int k0 = ks * 16 + (lane & 3) * 2;
            uint32_t a[4];
            a[0] = ldh2(&Qs[ar * QKS + k0]);
            a[1] = ldh2(&Qs[(ar + 8) * QKS + k0]);
            a[2] = ldh2(&Qs[ar * QKS + k0 + 8]);
            a[3] = ldh2(&Qs[(ar + 8) * QKS + k0 + 8]);
            #pragma unroll
            for (int nf = 0; nf < 2; nf++) {
                int br = wn * 16 + nf * 8 + (lane >> 2);
                uint32_t bb[2];
                bb[0] = ldh2(&Ks[br * QKS + k0]);
                bb[1] = ldh2(&Ks[br * QKS + k0 + 8]);
                mma_f16(s[nf], a, bb);
            }
        }

        // ---- key-padding mask + write S tile (fp32) to smem
        {
            const int r0 = wm * 16 + (lane >> 2);
            #pragma unroll
            for (int nf = 0; nf < 2; nf++) {
                int c0 = wn * 16 + nf * 8 + 2 * (lane & 3);
                int kg = kt * 64 + c0;
                float v0 = (kg     < len) ? s[nf][0] : -1e30f;
                float v1 = (kg + 1 < len) ? s[nf][1] : -1e30f;
                float v2 = (kg     < len) ? s[nf][2] : -1e30f;
                float v3 = (kg + 1 < len) ? s[nf][3] : -1e30f;
                Ss[r0 * SSF + c0]           = v0;
                Ss[r0 * SSF + c0 + 1]       = v1;
                Ss[(r0 + 8) * SSF + c0]     = v2;
                Ss[(r0 + 8) * SSF + c0 + 1] = v3;
            }
        }
        __syncthreads();   // S visible; all K reads done

        // ---- prefetch K[t+1] into the (now free) K buffer
        if (kt + 1 < nkt) {
            #pragma unroll
            for (int it = 0; it < 8; it++) {
                int idx = tid + it * 256;
                int r = idx >> 5, c8 = (idx & 31) * 8;
                cp16(&Ks[r * QKS + c8],
                     &g_K[kbase + (size_t)((kt + 1) * 64 + r) * HH + c8]);
            }
        }
        CP_COMMIT();

        // ---- online softmax: 8 threads per row, 8 cols each; emit P as fp16
        {
            const int row = tid >> 3, part = tid & 7;  // rows 0..31
            const float* srow = &Ss[row * SSF + part * 8];
            float4 p0 = *(const float4*)&srow[0];
            float4 p1 = *(const float4*)&srow[4];
            float mx = fmaxf(fmaxf(fmaxf(p0.x, p0.y), fmaxf(p0.z, p0.w)),
                             fmaxf(fmaxf(p1.x, p1.y), fmaxf(p1.z, p1.w)));
            mx = fmaxf(mx, __shfl_xor_sync(0xffffffffu, mx, 1));
            mx = fmaxf(mx, __shfl_xor_sync(0xffffffffu, mx, 2));
            mx = fmaxf(mx, __shfl_xor_sync(0xffffffffu, mx, 4));
            const float mold = rowm[row];
            const float mnew = fmaxf(mold, mx);
            p0.x = __expf(p0.x - mnew); p0.y = __expf(p0.y - mnew);
            p0.z = __expf(p0.z - mnew); p0.w = __expf(p0.w - mnew);
            p1.x = __expf(p1.x - mnew); p1.y = __expf(p1.y - mnew);
            p1.z = __expf(p1.z - mnew); p1.w = __expf(p1.w - mnew);
            float sum = (p0.x + p0.y) + (p0.z + p0.w)
                      + (p1.x + p1.y) + (p1.z + p1.w);
            __half2 h0 = __floats2half2_rn(p0.x, p0.y);
            __half2 h1 = __floats2half2_rn(p0.z, p0.w);
            __half2 h2 = __floats2half2_rn(p1.x, p1.y);
            __half2 h3 = __floats2half2_rn(p1.z, p1.w);
            uint4 u;
            u.x = *(uint32_t*)&h0; u.y = *(uint32_t*)&h1;
            u.z = *(uint32_t*)&h2; u.w = *(uint32_t*)&h3;
            *(uint4*)&Ps[row * PSS + part * 8] = u;
            sum += __shfl_xor_sync(0xffffffffu, sum, 1);
            sum += __shfl_xor_sync(0xffffffffu, sum, 2);
            sum += __shfl_xor_sync(0xffffffffu, sum, 4);
            if (part == 0) {
                float alpha = __expf(mold - mnew);
                rowa[row] = alpha;
                rowl[row] = rowl[row] * alpha + sum;
                rowm[row] = mnew;
            }
        }

        CP_WAIT1();            // Vt[t] done (K[t+1] may still be in flight)
        __syncthreads();       // P + rowa visible; Vt visible

        // ---- rescale O, accumulate O += P @ V (from transposed Vt)
        {
            const int r0 = wm * 16 + (lane >> 2);
            const float a0 = rowa[r0], a1 = rowa[r0 + 8];
            #pragma unroll
            for (int nf = 0; nf < 8; nf++) {
                o[nf][0] *= a0; o[nf][1] *= a0;
                o[nf][2] *= a1; o[nf][3] *= a1;
            }
            #pragma unroll
            for (int ks = 0; ks < 4; ks++) {           // 64 kv / 16
                const int k0 = ks * 16 + (lane & 3) * 2;
                uint32_t a[4];
                a[0] = ldh2(&Ps[r0 * PSS + k0]);
                a[1] = ldh2(&Ps[(r0 + 8) * PSS + k0]);
                a[2] = ldh2(&Ps[r0 * PSS + k0 + 8]);
                a[3] = ldh2(&Ps[(r0 + 8) * PSS + k0 + 8]);
                #pragma unroll
                for (int nf = 0; nf < 8; nf++) {
                    int bc = wn * 64 + nf * 8 + (lane >> 2);   // d row of Vt
                    uint32_t bb[2];
                    bb[0] = ldh2(&Vts[bc * VTS + k0]);
                    bb[1] = ldh2(&Vts[bc * VTS + k0 + 8]);
                    mma_f16(o[nf], a, bb);
                }
            }
        }
        __syncthreads();       // all Vt reads done

        // ---- prefetch Vt[t+1] into the (now free) Vt buffer
        if (kt + 1 < nkt) {
            #pragma unroll
            for (int it = 0; it < 8; it++) {
                int idx = tid + it * 256;
                int r = idx >> 3, c8 = (idx & 7) * 8;
                cp16(&Vts[r * VTS + c8],
                     &g_Vt[vtb + (size_t)r * LL + (kt + 1) * 64 + c8]);
            }
        }
        CP_COMMIT();
    }

    // ---- epilogue: O /= l, store
    {
        const int r0 = wm * 16 + (lane >> 2);
        const float inv0 = 1.f / rowl[r0];
        const float inv1 = 1.f / rowl[r0 + 8];
        const size_t base = (size_t)b * LL * HH;
        const size_t orow0 = base + (size_t)(qt * 32 + r0) * HH;
        const size_t orow1 = base + (size_t)(qt * 32 + r0 + 8) * HH;
        #pragma unroll
        for (int nf = 0; nf < 8; nf++) {
            int c0 = wn * 64 + nf * 8 + 2 * (lane & 3);
            out[orow0 + c0]     = o[nf][0] * inv0;
            out[orow0 + c0 + 1] = o[nf][1] * inv0;
            out[orow1 + c0]     = o[nf][2] * inv1;
            out[orow1 + c0 + 1] = o[nf][3] * inv1;
        }
    }
}

// ---------------------------------------------------------------------------
// Launch
// ---------------------------------------------------------------------------
extern "C" void kernel_launch(void* const* d_in, const int* in_sizes, int n_in,
                              void* d_out, int out_size)
{
    const float* x    = (const float*)d_in[0];
    const float* Wq   = (const float*)d_in[1];
    const float* Wk   = (const float*)d_in[2];
    const float* Wv   = (const float*)d_in[3];
    const int*   lens = (const int*)d_in[4];
    float* out = (float*)d_out;
    (void)in_sizes; (void)n_in; (void)out_size;

    cudaFuncSetAttribute(attn_kernel,
                         cudaFuncAttributeMaxDynamicSharedMemorySize,
                         ATTN_SMEM_BYTES);

    dim3 pgrid(M_TOT / 64, HH / 64, 3);
    proj_kernel<<<pgrid, 256>>>(x, Wq, Wk, Wv, lens);

    dim3 agrid(LL / 32, BB);
    attn_kernel<<<agrid, 256, ATTN_SMEM_BYTES>>>(lens, out);
}

// round 14
// speedup vs baseline: 1.0711x; 1.0711x over previous
#include <cuda_runtime.h>
#include <cuda_fp16.h>
#include <cstdint>

#define BB 8
#define LL 2048
#define HH 256
#define M_TOT (BB*LL)

// Scratch (static device globals — allocation-free, graph-capture legal)
__device__ __half g_Q[M_TOT*HH];          // [b*L + q][h], pre-scaled by 1/sqrt(H)
__device__ __half g_K[M_TOT*HH];          // [b*L + k][h]
__device__ __half g_Vt[BB*HH*LL];         // TRANSPOSED: [b][d][kv]

// ---------------------------------------------------------------------------
// Helpers
// ---------------------------------------------------------------------------
__device__ __forceinline__ void mma_f16(float c[4], const uint32_t a[4],
                                        uint32_t b0, uint32_t b1) {
    asm volatile(
        "mma.sync.aligned.m16n8k16.row.col.f32.f16.f16.f32 "
        "{%0,%1,%2,%3}, {%4,%5,%6,%7}, {%8,%9}, {%0,%1,%2,%3};"
        : "+f"(c[0]), "+f"(c[1]), "+f"(c[2]), "+f"(c[3])
        : "r"(a[0]), "r"(a[1]), "r"(a[2]), "r"(a[3]), "r"(b0), "r"(b1));
}
// ldmatrix x4: one instruction = 4 fragment registers (16x16 halves).
// Lane addressing (same for A and B operands, no .trans):
//   row = base_row + ((lane>>3)&1)*8 + (lane&7),  col = base_col + (lane>>4)*8
__device__ __forceinline__ void ldsm4(uint32_t r[4], const __half* p) {
    uint32_t sa = (uint32_t)__cvta_generic_to_shared(p);
    asm volatile("ldmatrix.sync.aligned.m8n8.x4.shared.b16 {%0,%1,%2,%3}, [%4];"
                 : "=r"(r[0]), "=r"(r[1]), "=r"(r[2]), "=r"(r[3]) : "r"(sa));
}
__device__ __forceinline__ void cp16(__half* s, const __half* g) {
    uint32_t sa = (uint32_t)__cvta_generic_to_shared(s);
    asm volatile("cp.async.cg.shared.global [%0], [%1], 16;" :: "r"(sa), "l"(g));
}
#define CP_COMMIT() asm volatile("cp.async.commit_group;" ::: "memory")
#define CP_WAIT1()  asm volatile("cp.async.wait_group 1;" ::: "memory")

// ---------------------------------------------------------------------------
// Kernel 1: QKV projection, y = x @ W^T, fp16 mma + ldmatrix fragments.
// grid (M_TOT/64, HH/64, 3), block 256 (8 warps, 4m x 2n of a 64x64 tile).
// ---------------------------------------------------------------------------
__global__ __launch_bounds__(256, 2)
void proj_kernel(const float* __restrict__ x,
                 const float* __restrict__ Wq,
                 const float* __restrict__ Wk,
                 const float* __restrict__ Wv,
                 const int* __restrict__ lens)
{
    const int mtile = blockIdx.x, ntile = blockIdx.y, which = blockIdx.z;
    const float* Wp = (which == 0) ? Wq : (which == 1) ? Wk : Wv;

    if (which != 0) {
        int m0 = mtile * 64;
        int b = m0 / LL, pos = m0 % LL;
        if (pos >= lens[b]) return;
    }

    __shared__ __half Xs[64][72];   // 144B stride ≡ 16 mod 128: LDSM conflict-free
    __shared__ __half Ws[64][72];

    const int tid = threadIdx.x;
    const int lane = tid & 31, warp = tid >> 5;
    const int wm = warp & 3, wn = warp >> 2;   // 4 x 2 warp grid
    const int lrow = ((lane >> 3) & 1) * 8 + (lane & 7);
    const int lcol = (lane >> 4) * 8;

    float acc[4][4];
    #pragma unroll
    for (int i = 0; i < 4; i++)
        #pragma unroll
        for (int j = 0; j < 4; j++) acc[i][j] = 0.f;

    for (int kc = 0; kc < HH; kc += 64) {
        #pragma unroll
        for (int it = 0; it < 4; it++) {
            int idx = tid + it * 256;          // 1024 float4 per operand
            int r = idx >> 4, c4 = (idx & 15) * 4;
            float4 xv = *(const float4*)&x[(size_t)(mtile * 64 + r) * HH + kc + c4];
            float4 wv = *(const float4*)&Wp[(size_t)(ntile * 64 + r) * HH + kc + c4];
            *(__half2*)&Xs[r][c4]     = __floats2half2_rn(xv.x, xv.y);
            *(__half2*)&Xs[r][c4 + 2] = __floats2half2_rn(xv.z, xv.w);
            *(__half2*)&Ws[r][c4]     = __floats2half2_rn(wv.x, wv.y);
            *(__half2*)&Ws[r][c4 + 2] = __floats2half2_rn(wv.z, wv.w);
        }
        __syncthreads();

        #pragma unroll
        for (int ks = 0; ks < 4; ks++) {       // k-steps of 16
            uint32_t a[4];
            ldsm4(a, &Xs[wm * 16 + lrow][ks * 16 + lcol]);
            #pragma unroll
            for (int nf2 = 0; nf2 < 2; nf2++) {  // two 16-wide n chunks
                uint32_t bv[4];
                ldsm4(bv, &Ws[wn * 32 + nf2 * 16 + lrow][ks * 16 + lcol]);
                mma_f16(acc[nf2 * 2],     a, bv[0], bv[2]);
                mma_f16(acc[nf2 * 2 + 1], a, bv[1], bv[3]);
            }
        }
        __syncthreads();
    }

    if (which != 2) {
        __half* outp = (which == 0) ? g_Q : g_K;
        const float scl = (which == 0) ? 0.0625f : 1.0f;
        const int r0 = mtile * 64 + wm * 16 + (lane >> 2);
        #pragma unroll
        for (int nf = 0; nf < 4; nf++) {
            int c0 = ntile * 64 + wn * 32 + nf * 8 + 2 * (lane & 3);
            *(__half2*)&outp[(size_t)r0 * HH + c0] =
                __floats2half2_rn(acc[nf][0] * scl, acc[nf][1] * scl);
            *(__half2*)&outp[(size_t)(r0 + 8) * HH + c0] =
                __floats2half2_rn(acc[nf][2] * scl, acc[nf][3] * scl);
        }
    } else {
        // V: stage tile in smem (reuse Xs), then write transposed [d][kv]
        const int rl = wm * 16 + (lane >> 2);
        #pragma unroll
        for (int nf = 0; nf < 4; nf++) {
            int cl = wn * 32 + nf * 8 + 2 * (lane & 3);
            *(__half2*)&Xs[rl][cl]     = __floats2half2_rn(acc[nf][0], acc[nf][1]);
            *(__half2*)&Xs[rl + 8][cl] = __floats2half2_rn(acc[nf][2], acc[nf][3]);
        }
        __syncthreads();
        const int d = tid >> 2, part = tid & 3;         // 64 d-rows x 4 parts
        const int m0 = mtile * 64;
        const int b = m0 >> 11, kvb = m0 & 2047;
        __align__(16) __half tmp[16];
        #pragma unroll
        for (int i = 0; i < 16; i++) tmp[i] = Xs[part * 16 + i][d];
        size_t vb = (size_t)b * HH * LL + (size_t)(ntile * 64 + d) * LL + kvb + part * 16;
        *(uint4*)&g_Vt[vb]     = *(uint4*)&tmp[0];
        *(uint4*)&g_Vt[vb + 8] = *(uint4*)&tmp[8];
    }
}

// ---------------------------------------------------------------------------
// Kernel 2: flash attention, fp16 + ldmatrix fragments (R5 shape otherwise).
// grid (LL/64, BB), block 512 (16 warps), 1 CTA/SM, cp.async K/V pipeline.
// ---------------------------------------------------------------------------
#define QKS 264   // 528B ≡ 16 mod 128 -> LDSM conflict-free
#define VTS 72    // 144B ≡ 16 mod 128
#define SSF 68
#define PSS 72

#define OFF_KS  33792
#define OFF_VT  67584
#define OFF_SS  104448
#define OFF_PS  121856
#define OFF_ST  131072
#define ATTN_SMEM_BYTES 131840

__global__ __launch_bounds__(512, 1)
void attn_kernel(const int* __restrict__ lens, float* __restrict__ out)
{
    extern __shared__ unsigned char smr[];
    __half* Qs  = (__half*)smr;
    __half* Ks  = (__half*)(smr + OFF_KS);
    __half* Vts = (__half*)(smr + OFF_VT);
    float*  Ss  = (float*)(smr + OFF_SS);
    __half* Ps  = (__half*)(smr + OFF_PS);
    float*  rowm = (float*)(smr + OFF_ST);
    float*  rowl = rowm + 64;
    float*  rowa = rowl + 64;

    const int qt = blockIdx.x, b = blockIdx.y;
    const int len = lens[b];
    const int tid = threadIdx.x, lane = tid & 31, warp = tid >> 5;
    const int wm = warp & 3, wn = warp >> 2;        // 4 x 4 warp grid
    const int lrow = ((lane >> 3) & 1) * 8 + (lane & 7);
    const int lcol = (lane >> 4) * 8;
    const size_t kbase = (size_t)b * LL * HH;
    const size_t vtb   = (size_t)b * HH * LL;
    const int nkt = (len + 63) >> 6;

    // Prologue: async-load K0 (group0) and Vt0 (group1)
    #pragma unroll
    for (int it = 0; it < 4; it++) {
        int idx = tid + it * 512;
        int r = idx >> 5, c8 = (idx & 31) * 8;
        cp16(&Ks[r * QKS + c8], &g_K[kbase + (size_t)r * HH + c8]);
    }
    CP_COMMIT();
    #pragma unroll
    for (int it = 0; it < 4; it++) {
        int idx = tid + it * 512;
        int r = idx >> 3, c8 = (idx & 7) * 8;
        cp16(&Vts[r * VTS + c8], &g_Vt[vtb + (size_t)r * LL + c8]);
    }
    CP_COMMIT();

    // Q tile (64 x 256 halves), already pre-scaled in projection
    #pragma unroll
    for (int it = 0; it < 4; it++) {
        int idx = tid + it * 512;
        int r = idx >> 5, c8 = (idx & 31) * 8;
        *(uint4*)&Qs[r * QKS + c8] =
            *(const uint4*)&g_Q[kbase + (size_t)(qt * 64 + r) * HH + c8];
    }
    if (tid < 64) { rowm[tid] = -1e30f; rowl[tid] = 0.f; }

    float o[8][4];
    #pragma unroll
    for (int i = 0; i < 8; i++)
        #pragma unroll
        for (int j = 0; j < 4; j++) o[i][j] = 0.f;

    // Per-warp LDSM base pointers
    const __half* qbase = &Qs[(wm * 16 + lrow) * QKS + lcol];
    const __half* kbase_s = &Ks[(wn * 16 + lrow) * QKS + lcol];
    const __half* pbase = &Ps[(wm * 16 + lrow) * PSS + lcol];

    for (int kt = 0; kt < nkt; kt++) {
        CP_WAIT1();            // K[t] done (Vt[t] may still be in flight)
        __syncthreads();

        // ---- S = Q K^T : warp rows [wm*16,+16), cols [wn*16,+16), k-dim 256
        float s[2][4];
        #pragma unroll
        for (int i = 0; i < 2; i++)
            #pragma unroll
            for (int j = 0; j < 4; j++) s[i][j] = 0.f;

        #pragma unroll
        for (int ks = 0; ks < 16; ks++) {              // k-steps of 16
            uint32_t a[4], bv[4];
            ldsm4(a, qbase + ks * 16);
            ldsm4(bv, kbase_s + ks * 16);
            mma_f16(s[0], a, bv[0], bv[2]);
            mma_f16(s[1], a, bv[1], bv[3]);
        }

        // ---- key-padding mask + write S tile (fp32) to smem
        {
            const int r0 = wm * 16 + (lane >> 2);
            #pragma unroll
            for (int nf = 0; nf < 2; nf++) {
                int c0 = wn * 16 + nf * 8 + 2 * (lane & 3);
                int kg = kt * 64 + c0;
                float v0 = (kg     < len) ? s[nf][0] : -1e30f;
                float v1 = (kg + 1 < len) ? s[nf][1] : -1e30f;
                float v2 = (kg     < len) ? s[nf][2] : -1e30f;
                float v3 = (kg + 1 < len) ? s[nf][3] : -1e30f;
                Ss[r0 * SSF + c0]           = v0;
                Ss[r0 * SSF + c0 + 1]       = v1;
                Ss[(r0 + 8) * SSF + c0]     = v2;
                Ss[(r0 + 8) * SSF + c0 + 1] = v3;
            }
        }
        __syncthreads();   // S visible; all K reads done

        // ---- prefetch K[t+1]
        if (kt + 1 < nkt) {
            #pragma unroll
            for (int it = 0; it < 4; it++) {
                int idx = tid + it * 512;
                int r = idx >> 5, c8 = (idx & 31) * 8;
                cp16(&Ks[r * QKS + c8],
                     &g_K[kbase + (size_t)((kt + 1) * 64 + r) * HH + c8]);
            }
        }
        CP_COMMIT();

        // ---- online softmax: 8 threads per row; emit P as fp16
        {
            const int row = tid >> 3, part = tid & 7;
            const float* srow = &Ss[row * SSF + part * 8];
            float4 p0 = *(const float4*)&srow[0];
            float4 p1 = *(const float4*)&srow[4];
            float mx = fmaxf(fmaxf(fmaxf(p0.x, p0.y), fmaxf(p0.z, p0.w)),
                             fmaxf(fmaxf(p1.x, p1.y), fmaxf(p1.z, p1.w)));
            mx = fmaxf(mx, __shfl_xor_sync(0xffffffffu, mx, 1));
            mx = fmaxf(mx, __shfl_xor_sync(0xffffffffu, mx, 2));
            mx = fmaxf(mx, __shfl_xor_sync(0xffffffffu, mx, 4));
            const float mold = rowm[row];
            const float mnew = fmaxf(mold, mx);
            p0.x = __expf(p0.x - mnew); p0.y = __expf(p0.y - mnew);
            p0.z = __expf(p0.z - mnew); p0.w = __expf(p0.w - mnew);
            p1.x = __expf(p1.x - mnew); p1.y = __expf(p1.y - mnew);
            p1.z = __expf(p1.z - mnew); p1.w = __expf(p1.w - mnew);
            float sum = (p0.x + p0.y) + (p0.z + p0.w)
                      + (p1.x + p1.y) + (p1.z + p1.w);
            __half2 h0 = __floats2half2_rn(p0.x, p0.y);
            __half2 h1 = __floats2half2_rn(p0.z, p0.w);
            __half2 h2 = __floats2half2_rn(p1.x, p1.y);
            __half2 h3 = __floats2half2_rn(p1.z, p1.w);
            uint4 u;
            u.x = *(uint32_t*)&h0; u.y = *(uint32_t*)&h1;
            u.z = *(uint32_t*)&h2; u.w = *(uint32_t*)&h3;
            *(uint4*)&Ps[row * PSS + part * 8] = u;
            sum += __shfl_xor_sync(0xffffffffu, sum, 1);
            sum += __shfl_xor_sync(0xffffffffu, sum, 2);
            sum += __shfl_xor_sync(0xffffffffu, sum, 4);
            if (part == 0) {
                float alpha = __expf(mold - mnew);
                rowa[row] = alpha;
                rowl[row] = rowl[row] * alpha + sum;
                rowm[row] = mnew;
            }
        }

        CP_WAIT1();            // Vt[t] done (K[t+1] may still be in flight)
        __syncthreads();       // P + rowa visible; Vt visible

        // ---- rescale O, accumulate O += P @ V (from transposed Vt)
        {
            const int r0 = wm * 16 + (lane >> 2);
            const float a0 = rowa[r0], a1 = rowa[r0 + 8];
            #pragma unroll
            for (int nf = 0; nf < 8; nf++) {
                o[nf][0] *= a0; o[nf][1] *= a0;
                o[nf][2] *= a1; o[nf][3] *= a1;
            }
            #pragma unroll
            for (int ks = 0; ks < 4; ks++) {           // 64 kv / 16
                uint32_t a[4];
                ldsm4(a, pbase + ks * 16);
                #pragma unroll
                for (int nf2 = 0; nf2 < 4; nf2++) {    // four 16-wide d chunks
                    uint32_t bv[4];
                    ldsm4(bv, &Vts[(wn * 64 + nf2 * 16 + lrow) * VTS
                                   + ks * 16 + lcol]);
                    mma_f16(o[nf2 * 2],     a, bv[0], bv[2]);
                    mma_f16(o[nf2 * 2 + 1], a, bv[1], bv[3]);
                }
            }
        }
        __syncthreads();       // all Vt reads done

        // ---- prefetch Vt[t+1]
        if (kt + 1 < nkt) {
            #pragma unroll
            for (int it = 0; it < 4; it++) {
                int idx = tid + it * 512;
                int r = idx >> 3, c8 = (idx & 7) * 8;
                cp16(&Vts[r * VTS + c8],
                     &g_Vt[vtb + (size_t)r * LL + (kt + 1) * 64 + c8]);
            }
        }
        CP_COMMIT();
    }

    // ---- epilogue: O /= l, store
    {
        const int r0 = wm * 16 + (lane >> 2);
        const float inv0 = 1.f / rowl[r0];
        const float inv1 = 1.f / rowl[r0 + 8];
        const size_t base = (size_t)b * LL * HH;
        const size_t orow0 = base + (size_t)(qt * 64 + r0) * HH;
        const size_t orow1 = base + (size_t)(qt * 64 + r0 + 8) * HH;
        #pragma unroll
        for (int nf = 0; nf < 8; nf++) {
            int c0 = wn * 64 + nf * 8 + 2 * (lane & 3);
            out[orow0 + c0]     = o[nf][0] * inv0;
            out[orow0 + c0 + 1] = o[nf][1] * inv0;
            out[orow1 + c0]     = o[nf][2] * inv1;
            out[orow1 + c0 + 1] = o[nf][3] * inv1;
        }
    }
}

// ---------------------------------------------------------------------------
// Launch
// ---------------------------------------------------------------------------
extern "C" void kernel_launch(void* const* d_in, const int* in_sizes, int n_in,
                              void* d_out, int out_size)
{
    const float* x    = (const float*)d_in[0];
    const float* Wq   = (const float*)d_in[1];
    const float* Wk   = (const float*)d_in[2];
    const float* Wv   = (const float*)d_in[3];
    const int*   lens = (const int*)d_in[4];
    float* out = (float*)d_out;
    (void)in_sizes; (void)n_in; (void)out_size;

    cudaFuncSetAttribute(attn_kernel,
                         cudaFuncAttributeMaxDynamicSharedMemorySize,
                         ATTN_SMEM_BYTES);

    dim3 pgrid(M_TOT / 64, HH / 64, 3);
    proj_kernel<<<pgrid, 256>>>(x, Wq, Wk, Wv, lens);

    dim3 agrid(LL / 64, BB);
    attn_kernel<<<agrid, 512, ATTN_SMEM_BYTES>>>(lens, out);
}

// round 16
// speedup vs baseline: 1.3694x; 1.2785x over previous
#include <cuda_runtime.h>
#include <cuda_fp16.h>
#include <cstdint>

#define BB 8
#define LL 2048
#define HH 256
#define M_TOT (BB*LL)

// Scratch (static device globals — allocation-free, graph-capture legal)
__device__ __half g_Q[M_TOT*HH];          // [b*L + q][h], pre-scaled by 1/sqrt(H)
__device__ __half g_K[M_TOT*HH];          // [b*L + k][h]
__device__ __half g_Vt[BB*HH*LL];         // TRANSPOSED: [b][d][kv]

// ---------------------------------------------------------------------------
// Helpers
// ---------------------------------------------------------------------------
__device__ __forceinline__ void mma_f16(float c[4], const uint32_t a[4],
                                        uint32_t b0, uint32_t b1) {
    asm volatile(
        "mma.sync.aligned.m16n8k16.row.col.f32.f16.f16.f32 "
        "{%0,%1,%2,%3}, {%4,%5,%6,%7}, {%8,%9}, {%0,%1,%2,%3};"
        : "+f"(c[0]), "+f"(c[1]), "+f"(c[2]), "+f"(c[3])
        : "r"(a[0]), "r"(a[1]), "r"(a[2]), "r"(a[3]), "r"(b0), "r"(b1));
}
// ldmatrix x4 (HW-verified lane map in R14):
//   row = base + ((lane>>3)&1)*8 + (lane&7),  col = base + (lane>>4)*8
//   bv[0]=rows0-7/k0-7, bv[1]=rows8-15/k0-7, bv[2]=rows0-7/k8-15, bv[3]=rows8-15/k8-15
__device__ __forceinline__ void ldsm4(uint32_t r[4], const __half* p) {
    uint32_t sa = (uint32_t)__cvta_generic_to_shared(p);
    asm volatile("ldmatrix.sync.aligned.m8n8.x4.shared.b16 {%0,%1,%2,%3}, [%4];"
                 : "=r"(r[0]), "=r"(r[1]), "=r"(r[2]), "=r"(r[3]) : "r"(sa));
}
__device__ __forceinline__ void cp16(__half* s, const __half* g) {
    uint32_t sa = (uint32_t)__cvta_generic_to_shared(s);
    asm volatile("cp.async.cg.shared.global [%0], [%1], 16;" :: "r"(sa), "l"(g));
}
#define CP_COMMIT() asm volatile("cp.async.commit_group;" ::: "memory")
#define CP_WAIT1()  asm volatile("cp.async.wait_group 1;" ::: "memory")
__device__ __forceinline__ uint32_t h2bits(__half2 h) { return *(uint32_t*)&h; }

// ---------------------------------------------------------------------------
// Kernel 1: QKV projection (unchanged from R14 — measured working)
// ---------------------------------------------------------------------------
__global__ __launch_bounds__(256, 2)
void proj_kernel(const float* __restrict__ x,
                 const float* __restrict__ Wq,
                 const float* __restrict__ Wk,
                 const float* __restrict__ Wv,
                 const int* __restrict__ lens)
{
    const int mtile = blockIdx.x, ntile = blockIdx.y, which = blockIdx.z;
    const float* Wp = (which == 0) ? Wq : (which == 1) ? Wk : Wv;

    if (which != 0) {
        int m0 = mtile * 64;
        int b = m0 / LL, pos = m0 % LL;
        if (pos >= lens[b]) return;
    }

    __shared__ __half Xs[64][72];
    __shared__ __half Ws[64][72];

    const int tid = threadIdx.x;
    const int lane = tid & 31, warp = tid >> 5;
    const int wm = warp & 3, wn = warp >> 2;
    const int lrow = ((lane >> 3) & 1) * 8 + (lane & 7);
    const int lcol = (lane >> 4) * 8;

    float acc[4][4];
    #pragma unroll
    for (int i = 0; i < 4; i++)
        #pragma unroll
        for (int j = 0; j < 4; j++) acc[i][j] = 0.f;

    for (int kc = 0; kc < HH; kc += 64) {
        #pragma unroll
        for (int it = 0; it < 4; it++) {
            int idx = tid + it * 256;
            int r = idx >> 4, c4 = (idx & 15) * 4;
            float4 xv = *(const float4*)&x[(size_t)(mtile * 64 + r) * HH + kc + c4];
            float4 wv = *(const float4*)&Wp[(size_t)(ntile * 64 + r) * HH + kc + c4];
            *(__half2*)&Xs[r][c4]     = __floats2half2_rn(xv.x, xv.y);
            *(__half2*)&Xs[r][c4 + 2] = __floats2half2_rn(xv.z, xv.w);
            *(__half2*)&Ws[r][c4]     = __floats2half2_rn(wv.x, wv.y);
            *(__half2*)&Ws[r][c4 + 2] = __floats2half2_rn(wv.z, wv.w);
        }
        __syncthreads();

        #pragma unroll
        for (int ks = 0; ks < 4; ks++) {
            uint32_t a[4];
            ldsm4(a, &Xs[wm * 16 + lrow][ks * 16 + lcol]);
            #pragma unroll
            for (int nf2 = 0; nf2 < 2; nf2++) {
                uint32_t bv[4];
                ldsm4(bv, &Ws[wn * 32 + nf2 * 16 + lrow][ks * 16 + lcol]);
                mma_f16(acc[nf2 * 2],     a, bv[0], bv[2]);
                mma_f16(acc[nf2 * 2 + 1], a, bv[1], bv[3]);
            }
        }
        __syncthreads();
    }

    if (which != 2) {
        __half* outp = (which == 0) ? g_Q : g_K;
        const float scl = (which == 0) ? 0.0625f : 1.0f;
        const int r0 = mtile * 64 + wm * 16 + (lane >> 2);
        #pragma unroll
        for (int nf = 0; nf < 4; nf++) {
            int c0 = ntile * 64 + wn * 32 + nf * 8 + 2 * (lane & 3);
            *(__half2*)&outp[(size_t)r0 * HH + c0] =
                __floats2half2_rn(acc[nf][0] * scl, acc[nf][1] * scl);
            *(__half2*)&outp[(size_t)(r0 + 8) * HH + c0] =
                __floats2half2_rn(acc[nf][2] * scl, acc[nf][3] * scl);
        }
    } else {
        const int rl = wm * 16 + (lane >> 2);
        #pragma unroll
        for (int nf = 0; nf < 4; nf++) {
            int cl = wn * 32 + nf * 8 + 2 * (lane & 3);
            *(__half2*)&Xs[rl][cl]     = __floats2half2_rn(acc[nf][0], acc[nf][1]);
            *(__half2*)&Xs[rl + 8][cl] = __floats2half2_rn(acc[nf][2], acc[nf][3]);
        }
        __syncthreads();
        const int d = tid >> 2, part = tid & 3;
        const int m0 = mtile * 64;
        const int b = m0 >> 11, kvb = m0 & 2047;
        __align__(16) __half tmp[16];
        #pragma unroll
        for (int i = 0; i < 16; i++) tmp[i] = Xs[part * 16 + i][d];
        size_t vb = (size_t)b * HH * LL + (size_t)(ntile * 64 + d) * LL + kvb + part * 16;
        *(uint4*)&g_Vt[vb]     = *(uint4*)&tmp[0];
        *(uint4*)&g_Vt[vb + 8] = *(uint4*)&tmp[8];
    }
}

// ---------------------------------------------------------------------------
// Kernel 2: FA2-style flash attention. grid (LL/128, BB), block 256 (8 warps).
// Each warp owns 16 q-rows entirely: S/P/softmax live in registers; smem is
// only Q (staging for LDSM) + K + Vt tiles. cp.async K/Vt ping-pong as before.
// ---------------------------------------------------------------------------
#define QKS 264   // 528B ≡ 16 mod 128 -> LDSM conflict-free
#define VTS 72    // 144B ≡ 16 mod 128

#define OFF_KS  67584                         // Qs: 128*264*2
#define OFF_VT  101376                        // Ks: 64*264*2
#define ATTN_SMEM_BYTES 138240                // Vts: 256*72*2

__global__ __launch_bounds__(256, 1)
void attn_kernel(const int* __restrict__ lens, float* __restrict__ out)
{
    extern __shared__ unsigned char smr[];
    __half* Qs  = (__half*)smr;               // 128 x QKS
    __half* Ks  = (__half*)(smr + OFF_KS);    // 64 x QKS
    __half* Vts = (__half*)(smr + OFF_VT);    // 256 x VTS

    const int qt = blockIdx.x, b = blockIdx.y;
    const int len = lens[b];
    const int tid = threadIdx.x, lane = tid & 31, warp = tid >> 5;
    const int lrow = ((lane >> 3) & 1) * 8 + (lane & 7);
    const int lcol = (lane >> 4) * 8;
    const size_t kbase = (size_t)b * LL * HH;
    const size_t vtb   = (size_t)b * HH * LL;
    const int nkt = (len + 63) >> 6;

    // Prologue: async-load K0 (group0) and Vt0 (group1)
    #pragma unroll
    for (int it = 0; it < 8; it++) {
        int idx = tid + it * 256;                  // 64 rows x 32 chunks
        int r = idx >> 5, c8 = (idx & 31) * 8;
        cp16(&Ks[r * QKS + c8], &g_K[kbase + (size_t)r * HH + c8]);
    }
    CP_COMMIT();
    #pragma unroll
    for (int it = 0; it < 8; it++) {
        int idx = tid + it * 256;                  // 256 rows x 8 chunks
        int r = idx >> 3, c8 = (idx & 7) * 8;
        cp16(&Vts[r * VTS + c8], &g_Vt[vtb + (size_t)r * LL + c8]);
    }
    CP_COMMIT();

    // Q tile (128 x 256 halves), pre-scaled in projection
    #pragma unroll
    for (int it = 0; it < 16; it++) {
        int idx = tid + it * 256;                  // 4096 uint4
        int r = idx >> 5, c8 = (idx & 31) * 8;
        *(uint4*)&Qs[r * QKS + c8] =
            *(const uint4*)&g_Q[kbase + (size_t)(qt * 128 + r) * HH + c8];
    }

    // Per-thread softmax state (rows r0 = warp*16 + lane>>2, r1 = r0+8)
    float m0 = -1e30f, m1 = -1e30f, l0 = 0.f, l1 = 0.f;

    // O accumulators: 32 n-frags (d-cols 8f..8f+7) x 4
    float o[32][4];
    #pragma unroll
    for (int f = 0; f < 32; f++)
        #pragma unroll
        for (int j = 0; j < 4; j++) o[f][j] = 0.f;

    const __half* qb = &Qs[(warp * 16 + lrow) * QKS + lcol];

    for (int kt = 0; kt < nkt; kt++) {
        CP_WAIT1();            // K[t] done (Vt[t] may still be in flight)
        __syncthreads();

        // ---- S = Q K^T : warp rows [warp*16,+16), ALL 64 cols, k-dim 256
        float s[8][4];
        #pragma unroll
        for (int j = 0; j < 8; j++)
            #pragma unroll
            for (int i = 0; i < 4; i++) s[j][i] = 0.f;

        #pragma unroll
        for (int ks = 0; ks < 16; ks++) {
            uint32_t a[4];
            ldsm4(a, qb + ks * 16);
            #pragma unroll
            for (int g = 0; g < 4; g++) {          // K row groups of 16
                uint32_t bv[4];
                ldsm4(bv, &Ks[(g * 16 + lrow) * QKS + ks * 16 + lcol]);
                mma_f16(s[2 * g],     a, bv[0], bv[2]);
                mma_f16(s[2 * g + 1], a, bv[1], bv[3]);
            }
        }
        __syncthreads();   // all K reads done

        // ---- prefetch K[t+1]
        if (kt + 1 < nkt) {
            #pragma unroll
            for (int it = 0; it < 8; it++) {
                int idx = tid + it * 256;
                int r = idx >> 5, c8 = (idx & 31) * 8;
                cp16(&Ks[r * QKS + c8],
                     &g_K[kbase + (size_t)((kt + 1) * 64 + r) * HH + c8]);
            }
        }
        CP_COMMIT();

        // ---- mask + online softmax, all in registers
        uint32_t pf[4][4];                         // P as mma A-fragments
        {
            const int cbase = kt * 64 + 2 * (lane & 3);
            float mx0 = -1e30f, mx1 = -1e30f;
            #pragma unroll
            for (int j = 0; j < 8; j++) {
                int kg = cbase + 8 * j;
                if (kg     >= len) { s[j][0] = -1e30f; s[j][2] = -1e30f; }
                if (kg + 1 >= len) { s[j][1] = -1e30f; s[j][3] = -1e30f; }
                mx0 = fmaxf(mx0, fmaxf(s[j][0], s[j][1]));
                mx1 = fmaxf(mx1, fmaxf(s[j][2], s[j][3]));
            }
            mx0 = fmaxf(mx0, __shfl_xor_sync(0xffffffffu, mx0, 1));
            mx0 = fmaxf(mx0, __shfl_xor_sync(0xffffffffu, mx0, 2));
            mx1 = fmaxf(mx1, __shfl_xor_sync(0xffffffffu, mx1, 1));
            mx1 = fmaxf(mx1, __shfl_xor_sync(0xffffffffu, mx1, 2));
            const float mn0 = fmaxf(m0, mx0);
            const float mn1 = fmaxf(m1, mx1);
            float sum0 = 0.f, sum1 = 0.f;
            #pragma unroll
            for (int j = 0; j < 8; j++) {
                float e0 = __expf(s[j][0] - mn0);
                float e1 = __expf(s[j][1] - mn0);
                float e2 = __expf(s[j][2] - mn1);
                float e3 = __expf(s[j][3] - mn1);
                sum0 += e0 + e1;
                sum1 += e2 + e3;
                pf[j >> 1][(j & 1) * 2 + 0] = h2bits(__floats2half2_rn(e0, e1));
                pf[j >> 1][(j & 1) * 2 + 1] = h2bits(__floats2half2_rn(e2, e3));
            }
            sum0 += __shfl_xor_sync(0xffffffffu, sum0, 1);
            sum0 += __shfl_xor_sync(0xffffffffu, sum0, 2);
            sum1 += __shfl_xor_sync(0xffffffffu, sum1, 1);
            sum1 += __shfl_xor_sync(0xffffffffu, sum1, 2);
            const float a0 = __expf(m0 - mn0);
            const float a1 = __expf(m1 - mn1);
            l0 = l0 * a0 + sum0;  m0 = mn0;
            l1 = l1 * a1 + sum1;  m1 = mn1;
            #pragma unroll
            for (int f = 0; f < 32; f++) {
                o[f][0] *= a0; o[f][1] *= a0;
                o[f][2] *= a1; o[f][3] *= a1;
            }
        }

        CP_WAIT1();            // Vt[t] done (K[t+1] may still be in flight)
        __syncthreads();       // Vt visible

        // ---- O += P @ V : P from registers, Vt via LDSM, all 256 d-cols
        #pragma unroll
        for (int ks = 0; ks < 4; ks++) {
            #pragma unroll
            for (int g = 0; g < 16; g++) {         // d groups of 16
                uint32_t bv[4];
                ldsm4(bv, &Vts[(g * 16 + lrow) * VTS + ks * 16 + lcol]);
                mma_f16(o[2 * g],     pf[ks], bv[0], bv[2]);
                mma_f16(o[2 * g + 1], pf[ks], bv[1], bv[3]);
            }
        }
        __syncthreads();       // all Vt reads done

        // ---- prefetch Vt[t+1]
        if (kt + 1 < nkt) {
            #pragma unroll
            for (int it = 0; it < 8; it++) {
                int idx = tid + it * 256;
                int r = idx >> 3, c8 = (idx & 7) * 8;
                cp16(&Vts[r * VTS + c8],
                     &g_Vt[vtb + (size_t)r * LL + (kt + 1) * 64 + c8]);
            }
        }
        CP_COMMIT();
    }

    // ---- epilogue: O /= l, store
    {
        const float inv0 = 1.f / l0;
        const float inv1 = 1.f / l1;
        const int r0 = qt * 128 + warp * 16 + (lane >> 2);
        const size_t base = (size_t)b * LL * HH;
        const size_t orow0 = base + (size_t)r0 * HH;
        const size_t orow1 = base + (size_t)(r0 + 8) * HH;
        #pragma unroll
        for (int f = 0; f < 32; f++) {
            int c0 = 8 * f + 2 * (lane & 3);
            out[orow0 + c0]     = o[f][0] * inv0;
            out[orow0 + c0 + 1] = o[f][1] * inv0;
            out[orow1 + c0]     = o[f][2] * inv1;
            out[orow1 + c0 + 1] = o[f][3] * inv1;
        }
    }
}

// ---------------------------------------------------------------------------
// Launch
// ---------------------------------------------------------------------------
extern "C" void kernel_launch(void* const* d_in, const int* in_sizes, int n_in,
                              void* d_out, int out_size)
{
    const float* x    = (const float*)d_in[0];
    const float* Wq   = (const float*)d_in[1];
    const float* Wk   = (const float*)d_in[2];
    const float* Wv   = (const float*)d_in[3];
    const int*   lens = (const int*)d_in[4];
    float* out = (float*)d_out;
    (void)in_sizes; (void)n_in; (void)out_size;

    cudaFuncSetAttribute(attn_kernel,
                         cudaFuncAttributeMaxDynamicSharedMemorySize,
                         ATTN_SMEM_BYTES);

    dim3 pgrid(M_TOT / 64, HH / 64, 3);
    proj_kernel<<<pgrid, 256>>>(x, Wq, Wk, Wv, lens);

    dim3 agrid(LL / 128, BB);
    attn_kernel<<<agrid, 256, ATTN_SMEM_BYTES>>>(lens, out);
}